// round 11
// baseline (speedup 1.0000x reference)
#include <cuda_runtime.h>
#include <cstdint>

#define M_DIM 32
#define K_DIM 16384
#define N_DIM 16384
#define SPLITS 8
#define KSPLIT (K_DIM / SPLITS)      // 2048
#define KCH 16                       // k rows per staged chunk
#define NCH (KSPLIT / KCH)           // 128 chunks per CTA
#define NB_TILE 256
#define THREADS 256
#define PADX 34                      // x row pitch in floats (136B: 8B-aligned)
#define STAGES 3

#define SV_FLOATS (KCH * NB_TILE)    // 4096 floats / buffer (16 KB)
#define SX_FLOATS (KCH * PADX)       // 544 floats / buffer (2.2 KB)
#define SMEM_BYTES (STAGES * (SV_FLOATS + SX_FLOATS) * 4)   // 55680 B

typedef unsigned long long ull;

// Static scratch (no allocation allowed)
__device__ float g_xT[K_DIM * M_DIM];            // 2 MB, xT[k][m] = relu(img)/128

__device__ __forceinline__ ull add2(ull a, ull b) {
    ull d;
    asm("add.rn.f32x2 %0, %1, %2;" : "=l"(d) : "l"(a), "l"(b));
    return d;
}
__device__ __forceinline__ void cp_async16(void* s, const void* g) {
    unsigned sa = (unsigned)__cvta_generic_to_shared(s);
    asm volatile("cp.async.cg.shared.global [%0], [%1], 16;" :: "r"(sa), "l"(g));
}
__device__ __forceinline__ void cp_async8(void* s, const void* g) {
    unsigned sa = (unsigned)__cvta_generic_to_shared(s);
    asm volatile("cp.async.ca.shared.global [%0], [%1], 8;" :: "r"(sa), "l"(g));
}

// ---------- kernel 1: transpose x (relu + /128) AND zero the poisoned out ----
__global__ void prep_xt_kernel(const float* __restrict__ img,
                               float4* __restrict__ out) {
    __shared__ float s[32][33];
    const int kb = blockIdx.x;                       // 512 tiles
    const int tx = threadIdx.x, ty = threadIdx.y;    // (32, 8)
    const int tid = ty * 32 + tx;

    // zero 1024 floats (256 float4) of out per CTA
    out[(size_t)kb * 256 + tid] = make_float4(0.f, 0.f, 0.f, 0.f);

    #pragma unroll
    for (int r = 0; r < 4; ++r) {
        int m = ty + 8 * r;
        s[tx][m] = img[(size_t)m * K_DIM + kb * 32 + tx];
    }
    __syncthreads();
    #pragma unroll
    for (int r = 0; r < 4; ++r) {
        int kl = ty + 8 * r;
        float v = s[kl][tx];
        g_xT[(size_t)(kb * 32 + kl) * M_DIM + tx] = fmaxf(v, 0.f) * (1.0f / 128.0f);
    }
}

// ---------- kernel 2: fused, 3-stage cp.async stream + ffs accumulate ----------
// grid (64 n-tiles, 8 k-splits) = 512 CTAs, 256 threads; thread owns one n, 32 m.
__global__ __launch_bounds__(THREADS, 4)
void spmm_fused(const float* __restrict__ V, float* __restrict__ out) {
    extern __shared__ __align__(16) float smem[];
    float* sv0 = smem;                           // STAGES x 16 KB V chunks
    float* sx0 = smem + STAGES * SV_FLOATS;      // STAGES x 2.2 KB x chunks

    const int nb = blockIdx.x, kb = blockIdx.y;
    const int tid = threadIdx.x;
    const int nloc = tid;                        // thread owns column nloc (0..255)
    const int n = nb * NB_TILE + nloc;

    ull acc[16];
    #pragma unroll
    for (int q = 0; q < 16; ++q) acc[q] = 0ull;

#define PREFETCH(cc, bb)                                                        \
    {                                                                           \
        const int pk0 = kb * KSPLIT + (cc) * KCH;                               \
        float* svb = sv0 + (bb) * SV_FLOATS;                                    \
        _Pragma("unroll")                                                       \
        for (int p = 0; p < 4; ++p) {          /* 16KB V chunk */               \
            int i = tid + p * THREADS;         /* 0..1023 float4 */             \
            int kk = i >> 6, q = i & 63;                                        \
            cp_async16(&svb[kk * NB_TILE + q * 4],                              \
                       V + (size_t)(pk0 + kk) * N_DIM + nb * NB_TILE + q * 4);  \
        }                                                                       \
        {                                      /* 2KB x chunk, padded rows */   \
            int kk = tid >> 4, q = tid & 15;                                    \
            cp_async8(&sx0[(bb) * SX_FLOATS + kk * PADX + q * 2],               \
                      g_xT + (size_t)(pk0 + kk) * M_DIM + q * 2);               \
        }                                                                       \
    }

    PREFETCH(0, 0)
    asm volatile("cp.async.commit_group;");
    PREFETCH(1, 1)
    asm volatile("cp.async.commit_group;");

    int buf = 0;
    for (int c = 0; c < NCH; ++c) {
        if (c + 2 < NCH) {
            int pb = buf + 2; if (pb >= STAGES) pb -= STAGES;
            PREFETCH(c + 2, pb)
        }
        asm volatile("cp.async.commit_group;");   // uniform group count per iter
        asm volatile("cp.async.wait_group 2;");   // chunk c landed
        __syncthreads();

        // build this thread's 16-bit k-word from its n column (conflict-free LDS)
        unsigned x = 0;
        const float* col = sv0 + buf * SV_FLOATS + nloc;
        #pragma unroll
        for (int j = 0; j < KCH; ++j) {
            if (col[j * NB_TILE] != 0.0f) x |= (1u << j);
        }
        // lane-private sparse walk
        const float* sxb = sx0 + buf * SX_FLOATS;
        while (x) {
            int j = __ffs(x) - 1;
            x &= x - 1;
            const ull* xr = (const ull*)(sxb + j * PADX);
            #pragma unroll
            for (int q = 0; q < 16; ++q) acc[q] = add2(acc[q], xr[q]);
        }
        __syncthreads();   // buf consumed; safe to overwrite
        if (++buf == STAGES) buf = 0;
    }
#undef PREFETCH

    // epilogue: combine split-K in place via no-return global reductions
    #pragma unroll
    for (int q = 0; q < 16; ++q) {
        float lo = __uint_as_float((unsigned)(acc[q] & 0xffffffffull));
        float hi = __uint_as_float((unsigned)(acc[q] >> 32));
        atomicAdd(&out[(size_t)(2 * q) * N_DIM + n], lo);
        atomicAdd(&out[(size_t)(2 * q + 1) * N_DIM + n], hi);
    }
}

extern "C" void kernel_launch(void* const* d_in, const int* in_sizes, int n_in,
                              void* d_out, int out_size) {
    const float* img = (const float*)d_in[0];   // (2,16,128,128)
    const float* V   = (const float*)d_in[1];   // (128,128,128,128)
    float* out = (float*)d_out;

    (void)in_sizes; (void)n_in; (void)out_size;

    cudaFuncSetAttribute(spmm_fused,
                         cudaFuncAttributeMaxDynamicSharedMemorySize, SMEM_BYTES);

    prep_xt_kernel<<<K_DIM / 32, dim3(32, 8)>>>(img, (float4*)out);

    dim3 grid(N_DIM / NB_TILE, SPLITS);   // (64, 8)
    spmm_fused<<<grid, THREADS, SMEM_BYTES>>>(V, out);
}

// round 12
// speedup vs baseline: 1.1103x; 1.1103x over previous
#include <cuda_runtime.h>
#include <cstdint>

#define M_DIM 32
#define K_DIM 16384
#define N_DIM 16384
#define SPLITS 8
#define KSPLIT (K_DIM / SPLITS)      // 2048
#define KCH 16                       // k rows per staged chunk
#define NCH (KSPLIT / KCH)           // 128 chunks per CTA
#define NB_TILE 256
#define PADX 34                      // x row pitch in floats (136B: 8B-aligned)

typedef unsigned long long ull;

// Static scratch (no allocation allowed)
__device__ float g_xT[K_DIM * M_DIM];            // 2 MB, xT[k][m] = relu(img)/128

__device__ __forceinline__ ull add2(ull a, ull b) {
    ull d;
    asm("add.rn.f32x2 %0, %1, %2;" : "=l"(d) : "l"(a), "l"(b));
    return d;
}
__device__ __forceinline__ void cp_async16(void* s, const void* g) {
    unsigned sa = (unsigned)__cvta_generic_to_shared(s);
    asm volatile("cp.async.cg.shared.global [%0], [%1], 16;" :: "r"(sa), "l"(g));
}
__device__ __forceinline__ void cp_async8(void* s, const void* g) {
    unsigned sa = (unsigned)__cvta_generic_to_shared(s);
    asm volatile("cp.async.ca.shared.global [%0], [%1], 8;" :: "r"(sa), "l"(g));
}

// ---------- kernel 1: transpose x (relu + /128) AND zero the poisoned out ----
__global__ void prep_xt_kernel(const float* __restrict__ img,
                               float4* __restrict__ out) {
    __shared__ float s[32][33];
    const int kb = blockIdx.x;                       // 512 tiles
    const int tx = threadIdx.x, ty = threadIdx.y;    // (32, 8)
    const int tid = ty * 32 + tx;

    // zero 1024 floats (256 float4) of out per CTA: 512*1024 = 524288 total
    out[(size_t)kb * 256 + tid] = make_float4(0.f, 0.f, 0.f, 0.f);

    #pragma unroll
    for (int r = 0; r < 4; ++r) {
        int m = ty + 8 * r;
        s[tx][m] = img[(size_t)m * K_DIM + kb * 32 + tx];
    }
    __syncthreads();
    #pragma unroll
    for (int r = 0; r < 4; ++r) {
        int kl = ty + 8 * r;
        float v = s[kl][tx];
        g_xT[(size_t)(kb * 32 + kl) * M_DIM + tx] = fmaxf(v, 0.f) * (1.0f / 128.0f);
    }
}

// ---------- kernel 2: fused, cp.async double-buffered stream + ffs accumulate --
// grid (64 n-tiles, 8 k-splits) = 512 CTAs, 256 threads; thread owns one n, 32 m.
__global__ __launch_bounds__(256, 4)
void spmm_fused(const float* __restrict__ V, float* __restrict__ out) {
    __shared__ __align__(16) float sv[2][KCH * NB_TILE];  // 2 x 16 KB
    __shared__ __align__(16) float sx[2][KCH * PADX];     // 2 x 2.2 KB

    const int nb = blockIdx.x, kb = blockIdx.y;
    const int tid = threadIdx.x;
    const int nloc = tid;                 // thread owns column nloc (0..255)
    const int n = nb * NB_TILE + nloc;

    ull acc[16];
    #pragma unroll
    for (int q = 0; q < 16; ++q) acc[q] = 0ull;

#define PREFETCH(cc, bb)                                                       \
    {                                                                          \
        const int pk0 = kb * KSPLIT + (cc) * KCH;                              \
        _Pragma("unroll")                                                      \
        for (int p = 0; p < 4; ++p) {          /* 16KB V chunk */              \
            int i = tid + p * 256;             /* 0..1023 float4 */            \
            int kk = i >> 6, q = i & 63;                                       \
            cp_async16(&sv[bb][kk * NB_TILE + q * 4],                          \
                       V + (size_t)(pk0 + kk) * N_DIM + nb * NB_TILE + q * 4); \
        }                                                                      \
        {                                      /* 2KB x chunk, padded rows */  \
            int kk = tid >> 4, q = tid & 15;                                   \
            cp_async8(&sx[bb][kk * PADX + q * 2],                              \
                      g_xT + (size_t)(pk0 + kk) * M_DIM + q * 2);              \
        }                                                                      \
    }

    PREFETCH(0, 0)
    asm volatile("cp.async.commit_group;");

    for (int c = 0; c < NCH; ++c) {
        const int buf = c & 1;
        if (c + 1 < NCH) PREFETCH(c + 1, (c + 1) & 1)
        asm volatile("cp.async.commit_group;");   // uniform group count
        asm volatile("cp.async.wait_group 1;");   // chunk c landed
        __syncthreads();

        // build this thread's 16-bit k-word from its n column (conflict-free LDS)
        unsigned x = 0;
        const float* col = &sv[buf][nloc];
        #pragma unroll
        for (int j = 0; j < KCH; ++j) {
            if (col[j * NB_TILE] != 0.0f) x |= (1u << j);
        }
        // lane-private sparse walk
        while (x) {
            int j = __ffs(x) - 1;
            x &= x - 1;
            const ull* xr = (const ull*)(&sx[buf][j * PADX]);
            #pragma unroll
            for (int q = 0; q < 16; ++q) acc[q] = add2(acc[q], xr[q]);
        }
        __syncthreads();   // buf consumed; safe to overwrite next iteration
    }
#undef PREFETCH

    // epilogue: combine split-K in place via no-return global reductions
    #pragma unroll
    for (int q = 0; q < 16; ++q) {
        float lo = __uint_as_float((unsigned)(acc[q] & 0xffffffffull));
        float hi = __uint_as_float((unsigned)(acc[q] >> 32));
        atomicAdd(&out[(size_t)(2 * q) * N_DIM + n], lo);
        atomicAdd(&out[(size_t)(2 * q + 1) * N_DIM + n], hi);
    }
}

extern "C" void kernel_launch(void* const* d_in, const int* in_sizes, int n_in,
                              void* d_out, int out_size) {
    const float* img = (const float*)d_in[0];   // (2,16,128,128)
    const float* V   = (const float*)d_in[1];   // (128,128,128,128)
    float* out = (float*)d_out;

    (void)in_sizes; (void)n_in; (void)out_size;

    prep_xt_kernel<<<K_DIM / 32, dim3(32, 8)>>>(img, (float4*)out);

    dim3 grid(N_DIM / NB_TILE, SPLITS);   // (64, 8)
    spmm_fused<<<grid, 256>>>(V, out);
}

// round 13
// speedup vs baseline: 1.1367x; 1.0238x over previous
#include <cuda_runtime.h>
#include <cstdint>

#define M_DIM 32
#define K_DIM 16384
#define N_DIM 16384
#define KCH 16                       // k rows per staged chunk
#define NCHT (K_DIM / KCH)           // 1024 total chunks per n-tile
#define KSPL 9                       // K splits (576 CTAs = 97% of 592 slots)
#define NB_TILE 256
#define PADX 34                      // x row pitch in floats (136B: 8B-aligned)

typedef unsigned long long ull;

// Static scratch (no allocation allowed)
__device__ float g_xT[K_DIM * M_DIM];            // 2 MB, xT[k][m] = relu(img)/128

__device__ __forceinline__ ull add2(ull a, ull b) {
    ull d;
    asm("add.rn.f32x2 %0, %1, %2;" : "=l"(d) : "l"(a), "l"(b));
    return d;
}
__device__ __forceinline__ void cp_async16(void* s, const void* g) {
    unsigned sa = (unsigned)__cvta_generic_to_shared(s);
    asm volatile("cp.async.cg.shared.global [%0], [%1], 16;" :: "r"(sa), "l"(g));
}
__device__ __forceinline__ void cp_async8(void* s, const void* g) {
    unsigned sa = (unsigned)__cvta_generic_to_shared(s);
    asm volatile("cp.async.ca.shared.global [%0], [%1], 8;" :: "r"(sa), "l"(g));
}

// ---------- kernel 1: transpose x (relu + /128) AND zero the poisoned out ----
__global__ void prep_xt_kernel(const float* __restrict__ img,
                               float4* __restrict__ out) {
    __shared__ float s[32][33];
    const int kb = blockIdx.x;                       // 512 tiles
    const int tx = threadIdx.x, ty = threadIdx.y;    // (32, 8)
    const int tid = ty * 32 + tx;

    // zero 1024 floats (256 float4) of out per CTA: 512*1024 = 524288 total
    out[(size_t)kb * 256 + tid] = make_float4(0.f, 0.f, 0.f, 0.f);

    #pragma unroll
    for (int r = 0; r < 4; ++r) {
        int m = ty + 8 * r;
        s[tx][m] = img[(size_t)m * K_DIM + kb * 32 + tx];
    }
    __syncthreads();
    #pragma unroll
    for (int r = 0; r < 4; ++r) {
        int kl = ty + 8 * r;
        float v = s[kl][tx];
        g_xT[(size_t)(kb * 32 + kl) * M_DIM + tx] = fmaxf(v, 0.f) * (1.0f / 128.0f);
    }
}

// ---------- kernel 2: fused, cp.async double-buffered stream + ffs accumulate --
// grid (64 n-tiles, 9 k-splits) = 576 CTAs, 256 threads; thread owns one n, 32 m.
// 1024 chunks per n-tile split 7x114 + 2x113 across the 9 kb's.
__global__ __launch_bounds__(256, 4)
void spmm_fused(const float* __restrict__ V, float* __restrict__ out) {
    __shared__ __align__(16) float sv[2][KCH * NB_TILE];  // 2 x 16 KB
    __shared__ __align__(16) float sx[2][KCH * PADX];     // 2 x 2.2 KB

    const int nb = blockIdx.x, kb = blockIdx.y;
    const int tid = threadIdx.x;
    const int nloc = tid;                 // thread owns column nloc (0..255)
    const int n = nb * NB_TILE + nloc;

    // chunk range for this k-split: first 7 splits get 114 chunks, last 2 get 113
    const int start = kb * 113 + (kb < 7 ? kb : 7);
    const int count = 113 + (kb < 7 ? 1 : 0);

    ull acc[16];
    #pragma unroll
    for (int q = 0; q < 16; ++q) acc[q] = 0ull;

#define PREFETCH(gg, bb)                                                       \
    {                                                                          \
        const int pk0 = (gg) * KCH;                                            \
        _Pragma("unroll")                                                      \
        for (int p = 0; p < 4; ++p) {          /* 16KB V chunk */              \
            int i = tid + p * 256;             /* 0..1023 float4 */            \
            int kk = i >> 6, q = i & 63;                                       \
            cp_async16(&sv[bb][kk * NB_TILE + q * 4],                          \
                       V + (size_t)(pk0 + kk) * N_DIM + nb * NB_TILE + q * 4); \
        }                                                                      \
        {                                      /* 2KB x chunk, padded rows */  \
            int kk = tid >> 4, q = tid & 15;                                   \
            cp_async8(&sx[bb][kk * PADX + q * 2],                              \
                      g_xT + (size_t)(pk0 + kk) * M_DIM + q * 2);              \
        }                                                                      \
    }

    PREFETCH(start, 0)
    asm volatile("cp.async.commit_group;");

    for (int c = 0; c < count; ++c) {
        const int buf = c & 1;
        if (c + 1 < count) PREFETCH(start + c + 1, (c + 1) & 1)
        asm volatile("cp.async.commit_group;");   // uniform group count
        asm volatile("cp.async.wait_group 1;");   // chunk c landed
        __syncthreads();

        // build this thread's 16-bit k-word from its n column (conflict-free LDS)
        unsigned x = 0;
        const float* col = &sv[buf][nloc];
        #pragma unroll
        for (int j = 0; j < KCH; ++j) {
            if (col[j * NB_TILE] != 0.0f) x |= (1u << j);
        }
        // lane-private sparse walk
        while (x) {
            int j = __ffs(x) - 1;
            x &= x - 1;
            const ull* xr = (const ull*)(&sx[buf][j * PADX]);
            #pragma unroll
            for (int q = 0; q < 16; ++q) acc[q] = add2(acc[q], xr[q]);
        }
        __syncthreads();   // buf consumed; safe to overwrite next iteration
    }
#undef PREFETCH

    // epilogue: combine split-K in place via no-return global reductions
    #pragma unroll
    for (int q = 0; q < 16; ++q) {
        float lo = __uint_as_float((unsigned)(acc[q] & 0xffffffffull));
        float hi = __uint_as_float((unsigned)(acc[q] >> 32));
        atomicAdd(&out[(size_t)(2 * q) * N_DIM + n], lo);
        atomicAdd(&out[(size_t)(2 * q + 1) * N_DIM + n], hi);
    }
}

extern "C" void kernel_launch(void* const* d_in, const int* in_sizes, int n_in,
                              void* d_out, int out_size) {
    const float* img = (const float*)d_in[0];   // (2,16,128,128)
    const float* V   = (const float*)d_in[1];   // (128,128,128,128)
    float* out = (float*)d_out;

    (void)in_sizes; (void)n_in; (void)out_size;

    prep_xt_kernel<<<K_DIM / 32, dim3(32, 8)>>>(img, (float4*)out);

    dim3 grid(N_DIM / NB_TILE, KSPL);   // (64, 9) = 576 CTAs
    spmm_fused<<<grid, 256>>>(V, out);
}